// round 12
// baseline (speedup 1.0000x reference)
#include <cuda_runtime.h>
#include <math.h>
#include <stdint.h>

// ---------------------------------------------------------------------------
// ExpressionBert forward. tf32 mma.sync + cp.async pipelines.
// Round 12: fragment loads via ldmatrix.x4 (24 ld-ops/chunk instead of 96
// scalar LDS) in gemm_pipe and fused_attn; everything else as round 11.
// ---------------------------------------------------------------------------

#define LNUM   4
#define DIM    512
#define NHEAD  4
#define DHD    128
#define FFI    128
#define SEQ    256
#define BATCH  128
#define NFEAT  6
#define TOK    (BATCH*SEQ)          // 32768
#define ROWSBH (BATCH*NHEAD*SEQ)    // 131072
#define QCOLS  384
#define DPAD   608

#define SM_SCALE 0.08838834764831845f  // 1/sqrt(128)

// ------------------------- static device scratch ---------------------------
__device__ float g_X  [TOK*DIM];
__device__ float g_Q  [TOK*DIM];
__device__ float g_K  [TOK*DIM];
__device__ float g_V  [TOK*DIM];
__device__ float g_CTX[TOK*DIM];
__device__ float g_TMP[TOK*DIM];
__device__ float g_Hb [TOK*FFI];
__device__ float g_QD [(size_t)ROWSBH*QCOLS];
__device__ float g_KD [(size_t)ROWSBH*QCOLS];
__device__ float g_dP [DPAD*DHD];

__device__ float g_WqT [LNUM*DIM*DIM];
__device__ float g_WkT [LNUM*DIM*DIM];
__device__ float g_WvT [LNUM*DIM*DIM];
__device__ float g_WoT [LNUM*DIM*DIM];
__device__ float g_WiT [LNUM*FFI*DIM];
__device__ float g_Wo2T[LNUM*DIM*FFI];

// ------------------------------ helpers -------------------------------------
__device__ __forceinline__ uint32_t smem_u32(const void* p) {
    uint32_t a;
    asm("{ .reg .u64 t; cvta.to.shared.u64 t, %1; cvt.u32.u64 %0, t; }"
        : "=r"(a) : "l"(p));
    return a;
}

__device__ __forceinline__ float gelu_exact(float x) {
    return 0.5f * x * (1.0f + erff(x * 0.70710678118654752440f));
}

__device__ __forceinline__ float tf32_rna(float f) {
    uint32_t u;
    asm("cvt.rna.tf32.f32 %0, %1;" : "=r"(u) : "f"(f));
    return __uint_as_float(u);
}

__device__ __forceinline__ void mma_tf32(float* d, const uint32_t* a,
                                         const uint32_t* b) {
    asm volatile(
        "mma.sync.aligned.m16n8k8.row.col.f32.tf32.tf32.f32 "
        "{%0,%1,%2,%3}, {%4,%5,%6,%7}, {%8,%9}, {%0,%1,%2,%3};"
        : "+f"(d[0]), "+f"(d[1]), "+f"(d[2]), "+f"(d[3])
        : "r"(a[0]), "r"(a[1]), "r"(a[2]), "r"(a[3]), "r"(b[0]), "r"(b[1]));
}

__device__ __forceinline__ void ldsm_x4(uint32_t& r0, uint32_t& r1,
                                        uint32_t& r2, uint32_t& r3, uint32_t addr) {
    asm volatile("ldmatrix.sync.aligned.m8n8.x4.shared.b16 {%0,%1,%2,%3}, [%4];"
                 : "=r"(r0), "=r"(r1), "=r"(r2), "=r"(r3) : "r"(addr));
}

__device__ __forceinline__ void cp16(uint32_t saddr, const void* gptr) {
    asm volatile("cp.async.cg.shared.global [%0], [%1], 16;"
                 :: "r"(saddr), "l"(gptr) : "memory");
}
#define CP_COMMIT() asm volatile("cp.async.commit_group;" ::: "memory")
#define CP_WAIT1()  asm volatile("cp.async.wait_group 1;" ::: "memory")

#define SST 36
#define STAGEF 9216
#define NSTAGE 3

// -------------- pipelined tf32 GEMM, 3-stage ring, ldmatrix frags -----------
// C = A @ Beff^T + bias (+GELU) (+R residual). MODE 0 plain, 1 QD, 2 KD.
template<int GELU, int MODE, int RESID>
__global__ __launch_bounds__(256, 2) void gemm_pipe(
    const float* __restrict__ A, const float* __restrict__ BT,
    const float* __restrict__ bias, const float* __restrict__ R,
    float* __restrict__ C, int K, int N) {
    extern __shared__ float dsm[];
    int tid  = threadIdx.x;
    int wid  = tid >> 5, lane = tid & 31;
    int g    = lane >> 2, t = lane & 3;
    int m0   = blockIdx.y * 128;
    int n0   = blockIdx.x * 128;
    int wm   = wid >> 1, wn = wid & 1;
    int mbase = wm * 32, nbase = wn * 64;

    // ldmatrix per-thread fragment-source coordinates
    int m_idx  = lane >> 3;                  // which 8x8 tile (0..3)
    int fr_row = ((m_idx & 1) << 3) + (lane & 7);   // 0..15
    int fr_col = (m_idx >> 1) << 2;                 // 0 or 4 (word col)
    // byte offsets within a stage, invariant across chunks (add kk*4 in-loop)
    uint32_t offA[2], offB[4];
    #pragma unroll
    for (int mt = 0; mt < 2; mt++)
        offA[mt] = (uint32_t)(((mbase + mt * 16 + fr_row) * SST + fr_col) * 4);
    #pragma unroll
    for (int np = 0; np < 4; np++)
        offB[np] = (uint32_t)(((nbase + np * 16 + fr_row) * SST + fr_col) * 4);

    const float* Beff = BT;
    if (MODE == 1) Beff = BT + (size_t)((m0 & 1023) >> 2) * K;
    if (MODE == 2) Beff = BT + (size_t)(224 - ((m0 & 1023) >> 2)) * K;

    float acc[2][8][4];
    #pragma unroll
    for (int i = 0; i < 2; i++)
        #pragma unroll
        for (int j = 0; j < 8; j++)
            #pragma unroll
            for (int q = 0; q < 4; q++) acc[i][j][q] = 0.0f;

    int nch = K >> 5;
    uint32_t dsm0 = smem_u32(dsm);

    // prologue: prefetch chunks 0 and 1
    #pragma unroll
    for (int s = 0; s < 2; s++) {
        float* sA = dsm + s * STAGEF;
        float* sB = sA + 4608;
        #pragma unroll
        for (int i = 0; i < 4; i++) {
            int idx = tid + i * 256, row = idx >> 3, seg = idx & 7;
            cp16(smem_u32(sA + row * SST + seg * 4),
                 &A[(size_t)(m0 + row) * K + s * 32 + seg * 4]);
            cp16(smem_u32(sB + row * SST + seg * 4),
                 &Beff[(size_t)(n0 + row) * K + s * 32 + seg * 4]);
        }
        CP_COMMIT();
    }

    int stage = 0;
    for (int c = 0; c < nch; c++) {
        CP_WAIT1();
        __syncthreads();
        if (c + 2 < nch) {
            int s = (stage + 2) % NSTAGE;
            float* sA = dsm + s * STAGEF;
            float* sB = sA + 4608;
            #pragma unroll
            for (int i = 0; i < 4; i++) {
                int idx = tid + i * 256, row = idx >> 3, seg = idx & 7;
                cp16(smem_u32(sA + row * SST + seg * 4),
                     &A[(size_t)(m0 + row) * K + (c + 2) * 32 + seg * 4]);
                cp16(smem_u32(sB + row * SST + seg * 4),
                     &Beff[(size_t)(n0 + row) * K + (c + 2) * 32 + seg * 4]);
            }
        }
        CP_COMMIT();
        uint32_t aBase = dsm0 + (uint32_t)(stage * STAGEF * 4);
        uint32_t bBase = aBase + 4608 * 4;
        #pragma unroll
        for (int kk = 0; kk < 32; kk += 8) {
            uint32_t af[2][4];
            #pragma unroll
            for (int mt = 0; mt < 2; mt++)
                ldsm_x4(af[mt][0], af[mt][1], af[mt][2], af[mt][3],
                        aBase + offA[mt] + kk * 4);
            uint32_t bf[8][2];
            #pragma unroll
            for (int np = 0; np < 4; np++) {
                uint32_t r0, r1, r2, r3;
                ldsm_x4(r0, r1, r2, r3, bBase + offB[np] + kk * 4);
                bf[2 * np + 0][0] = r0; bf[2 * np + 0][1] = r2;
                bf[2 * np + 1][0] = r1; bf[2 * np + 1][1] = r3;
            }
            #pragma unroll
            for (int mt = 0; mt < 2; mt++)
                #pragma unroll
                for (int nt = 0; nt < 8; nt++)
                    mma_tf32(acc[mt][nt], af[mt], bf[nt]);
        }
        stage = (stage + 1) % NSTAGE;
    }

    #pragma unroll
    for (int mt = 0; mt < 2; mt++) {
        #pragma unroll
        for (int nt = 0; nt < 8; nt++) {
            int col = n0 + nbase + nt * 8 + 2 * t;
            float b0 = bias ? bias[col]     : 0.0f;
            float b1 = bias ? bias[col + 1] : 0.0f;
            int r0 = m0 + mbase + mt * 16 + g;
            int r1 = r0 + 8;
            float v00 = acc[mt][nt][0] + b0, v01 = acc[mt][nt][1] + b1;
            float v10 = acc[mt][nt][2] + b0, v11 = acc[mt][nt][3] + b1;
            if (GELU) {
                v00 = gelu_exact(v00); v01 = gelu_exact(v01);
                v10 = gelu_exact(v10); v11 = gelu_exact(v11);
            }
            if (RESID) {
                float2 x0 = *reinterpret_cast<const float2*>(&R[(size_t)r0 * N + col]);
                float2 x1 = *reinterpret_cast<const float2*>(&R[(size_t)r1 * N + col]);
                v00 += x0.x; v01 += x0.y;
                v10 += x1.x; v11 += x1.y;
            }
            *reinterpret_cast<float2*>(&C[(size_t)r0 * N + col]) = make_float2(v00, v01);
            *reinterpret_cast<float2*>(&C[(size_t)r1 * N + col]) = make_float2(v10, v11);
        }
    }
}

// ------------- fused attention: scores + softmax + ctx ----------------------
#define PST 260
#define VST 132
#define OFF_Q0  0
#define OFF_Q1  4608
#define OFF_K0  9216
#define OFF_K1  18432
#define OFF_P   0
#define OFF_V0  33280
#define OFF_V1  37504
#define OFF_RED 41728
#define FUSED_SMEMF 42240

__global__ __launch_bounds__(256) void fused_attn(
    const float* __restrict__ Q, const float* __restrict__ Km,
    const float* __restrict__ V,
    const float* __restrict__ QD, const float* __restrict__ KD,
    const float* __restrict__ mask, float* __restrict__ CTX) {
    extern __shared__ float dsm[];
    int tid  = threadIdx.x;
    int wid  = tid >> 5, lane = tid & 31;
    int g    = lane >> 2, t = lane & 3;
    int l0   = blockIdx.x * 128;
    int bh   = blockIdx.y;
    int b    = bh >> 2, h = bh & 3;
    int wm   = wid >> 1, wn = wid & 1;
    int mbase = wm * 32;
    int nbase2 = wn * 64;

    int m_idx  = lane >> 3;
    int fr_row = ((m_idx & 1) << 3) + (lane & 7);
    int fr_col = (m_idx >> 1) << 2;
    uint32_t dsm0 = smem_u32(dsm);

    const float* Qb = Q  + (size_t)b * SEQ * DIM + h * DHD;
    const float* Kb = Km + (size_t)b * SEQ * DIM + h * DHD;
    const float* Vb = V  + (size_t)b * SEQ * DIM + h * DHD;

    float acc[2][16][4];
    #pragma unroll
    for (int i = 0; i < 2; i++)
        #pragma unroll
        for (int j = 0; j < 16; j++)
            #pragma unroll
            for (int q = 0; q < 4; q++) acc[i][j][q] = 0.0f;

    uint32_t offA[2], offK[8];
    #pragma unroll
    for (int mt = 0; mt < 2; mt++)
        offA[mt] = (uint32_t)(((mbase + mt * 16 + fr_row) * SST + fr_col) * 4);
    #pragma unroll
    for (int np = 0; np < 8; np++)
        offK[np] = (uint32_t)(((wn * 128 + np * 16 + fr_row) * SST + fr_col) * 4);

    {
        float* sQ = dsm + OFF_Q0;
        float* sK = dsm + OFF_K0;
        #pragma unroll
        for (int i = 0; i < 4; i++) {
            int idx = tid + i * 256, row = idx >> 3, seg = idx & 7;
            cp16(smem_u32(sQ + row * SST + seg * 4),
                 &Qb[(size_t)(l0 + row) * DIM + seg * 4]);
        }
        #pragma unroll
        for (int i = 0; i < 8; i++) {
            int idx = tid + i * 256, row = idx >> 3, seg = idx & 7;
            cp16(smem_u32(sK + row * SST + seg * 4),
                 &Kb[(size_t)row * DIM + seg * 4]);
        }
        CP_COMMIT();
    }
    for (int c = 0; c < 4; c++) {
        if (c + 1 < 4) {
            float* sQ = dsm + ((c + 1) & 1 ? OFF_Q1 : OFF_Q0);
            float* sK = dsm + ((c + 1) & 1 ? OFF_K1 : OFF_K0);
            #pragma unroll
            for (int i = 0; i < 4; i++) {
                int idx = tid + i * 256, row = idx >> 3, seg = idx & 7;
                cp16(smem_u32(sQ + row * SST + seg * 4),
                     &Qb[(size_t)(l0 + row) * DIM + (c + 1) * 32 + seg * 4]);
            }
            #pragma unroll
            for (int i = 0; i < 8; i++) {
                int idx = tid + i * 256, row = idx >> 3, seg = idx & 7;
                cp16(smem_u32(sK + row * SST + seg * 4),
                     &Kb[(size_t)row * DIM + (c + 1) * 32 + seg * 4]);
            }
            CP_COMMIT();
        } else {
            CP_COMMIT();
        }
        CP_WAIT1();
        __syncthreads();
        uint32_t qBase = dsm0 + (uint32_t)(((c & 1) ? OFF_Q1 : OFF_Q0) * 4);
        uint32_t kBase = dsm0 + (uint32_t)(((c & 1) ? OFF_K1 : OFF_K0) * 4);
        #pragma unroll
        for (int kk = 0; kk < 32; kk += 8) {
            uint32_t af[2][4];
            #pragma unroll
            for (int mt = 0; mt < 2; mt++)
                ldsm_x4(af[mt][0], af[mt][1], af[mt][2], af[mt][3],
                        qBase + offA[mt] + kk * 4);
            #pragma unroll
            for (int np = 0; np < 8; np++) {
                uint32_t r0, r1, r2, r3;
                ldsm_x4(r0, r1, r2, r3, kBase + offK[np] + kk * 4);
                uint32_t bf0[2] = {r0, r2};
                uint32_t bf1[2] = {r1, r3};
                #pragma unroll
                for (int mt = 0; mt < 2; mt++) {
                    mma_tf32(acc[mt][2 * np + 0], af[mt], bf0);
                    mma_tf32(acc[mt][2 * np + 1], af[mt], bf1);
                }
            }
        }
        __syncthreads();
    }

    #pragma unroll
    for (int mt = 0; mt < 2; mt++) {
        int ll0 = l0 + mbase + mt * 16 + g;
        int ll1 = ll0 + 8;
        size_t qdr0 = ((size_t)(b * SEQ + ll0) * NHEAD + h) * QCOLS;
        size_t qdr1 = ((size_t)(b * SEQ + ll1) * NHEAD + h) * QCOLS;
        #pragma unroll
        for (int nt = 0; nt < 16; nt++) {
            int rr0 = wn * 128 + nt * 8 + 2 * t;
            int rr1 = rr0 + 1;
            size_t kdr0 = ((size_t)(b * SEQ + rr0) * NHEAD + h) * QCOLS;
            size_t kdr1 = ((size_t)(b * SEQ + rr1) * NHEAD + h) * QCOLS;
            float bias0 = (1.0f - mask[b * SEQ + rr0]) * (-1e9f);
            float bias1 = (1.0f - mask[b * SEQ + rr1]) * (-1e9f);
            int jq00 = (ll0 & 31) + 255 - rr0, jq01 = jq00 - 1;
            int jq10 = (ll1 & 31) + 255 - rr0, jq11 = jq10 - 1;
            int jk00 = ll0 - (rr0 & 31) + 31,  jk01 = ll0 - (rr1 & 31) + 31;
            int jk10 = ll1 - (rr0 & 31) + 31,  jk11 = ll1 - (rr1 & 31) + 31;
            acc[mt][nt][0] = (acc[mt][nt][0] + QD[qdr0 + jq00] + KD[kdr0 + jk00]) * SM_SCALE + bias0;
            acc[mt][nt][1] = (acc[mt][nt][1] + QD[qdr0 + jq01] + KD[kdr1 + jk01]) * SM_SCALE + bias1;
            acc[mt][nt][2] = (acc[mt][nt][2] + QD[qdr1 + jq10] + KD[kdr0 + jk10]) * SM_SCALE + bias0;
            acc[mt][nt][3] = (acc[mt][nt][3] + QD[qdr1 + jq11] + KD[kdr1 + jk11]) * SM_SCALE + bias1;
        }
    }

    float* rmax = dsm + OFF_RED;
    float* rsum = dsm + OFF_RED + 256;
    float mx[2][2];
    #pragma unroll
    for (int mt = 0; mt < 2; mt++)
        #pragma unroll
        for (int hf = 0; hf < 2; hf++) {
            float m = -1e30f;
            #pragma unroll
            for (int nt = 0; nt < 16; nt++) {
                m = fmaxf(m, acc[mt][nt][hf * 2]);
                m = fmaxf(m, acc[mt][nt][hf * 2 + 1]);
            }
            m = fmaxf(m, __shfl_xor_sync(0xffffffffu, m, 1));
            m = fmaxf(m, __shfl_xor_sync(0xffffffffu, m, 2));
            mx[mt][hf] = m;
        }
    if (t == 0) {
        #pragma unroll
        for (int mt = 0; mt < 2; mt++)
            #pragma unroll
            for (int hf = 0; hf < 2; hf++) {
                int lrow = mbase + mt * 16 + hf * 8 + g;
                rmax[wn * 128 + lrow] = mx[mt][hf];
            }
    }
    __syncthreads();
    #pragma unroll
    for (int mt = 0; mt < 2; mt++)
        #pragma unroll
        for (int hf = 0; hf < 2; hf++) {
            int lrow = mbase + mt * 16 + hf * 8 + g;
            float m = fmaxf(rmax[lrow], rmax[128 + lrow]);
            float s = 0.0f;
            #pragma unroll
            for (int nt = 0; nt < 16; nt++) {
                float e0 = __expf(acc[mt][nt][hf * 2]     - m);
                float e1 = __expf(acc[mt][nt][hf * 2 + 1] - m);
                acc[mt][nt][hf * 2]     = e0;
                acc[mt][nt][hf * 2 + 1] = e1;
                s += e0 + e1;
            }
            s += __shfl_xor_sync(0xffffffffu, s, 1);
            s += __shfl_xor_sync(0xffffffffu, s, 2);
            if (t == 0) rsum[wn * 128 + lrow] = s;
        }
    __syncthreads();
    #pragma unroll
    for (int mt = 0; mt < 2; mt++)
        #pragma unroll
        for (int hf = 0; hf < 2; hf++) {
            int lrow = mbase + mt * 16 + hf * 8 + g;
            float inv = 1.0f / (rsum[lrow] + rsum[128 + lrow]);
            #pragma unroll
            for (int nt = 0; nt < 16; nt++) {
                acc[mt][nt][hf * 2]     *= inv;
                acc[mt][nt][hf * 2 + 1] *= inv;
            }
        }
    __syncthreads();

    float* P = dsm + OFF_P;
    #pragma unroll
    for (int mt = 0; mt < 2; mt++) {
        int lr0 = mbase + mt * 16 + g;
        int lr1 = lr0 + 8;
        #pragma unroll
        for (int nt = 0; nt < 16; nt++) {
            int col = wn * 128 + nt * 8 + 2 * t;
            *reinterpret_cast<float2*>(&P[lr0 * PST + col]) =
                make_float2(acc[mt][nt][0], acc[mt][nt][1]);
            *reinterpret_cast<float2*>(&P[lr1 * PST + col]) =
                make_float2(acc[mt][nt][2], acc[mt][nt][3]);
        }
    }
    __syncthreads();

    float acc2[2][8][4];
    #pragma unroll
    for (int i = 0; i < 2; i++)
        #pragma unroll
        for (int j = 0; j < 8; j++)
            #pragma unroll
            for (int q = 0; q < 4; q++) acc2[i][j][q] = 0.0f;

    uint32_t offP[2];
    #pragma unroll
    for (int mt = 0; mt < 2; mt++)
        offP[mt] = (uint32_t)(((mbase + mt * 16 + fr_row) * PST + fr_col) * 4);
    uint32_t pBase = dsm0 + OFF_P * 4;

    {
        float* sV = dsm + OFF_V0;
        #pragma unroll
        for (int i = 0; i < 4; i++) {
            int idx = tid + i * 256, r = idx >> 5, dseg = idx & 31;
            cp16(smem_u32(sV + r * VST + dseg * 4),
                 &Vb[(size_t)r * DIM + dseg * 4]);
        }
        CP_COMMIT();
    }
    for (int c = 0; c < 8; c++) {
        if (c + 1 < 8) {
            float* sV = dsm + (((c + 1) & 1) ? OFF_V1 : OFF_V0);
            #pragma unroll
            for (int i = 0; i < 4; i++) {
                int idx = tid + i * 256, r = idx >> 5, dseg = idx & 31;
                cp16(smem_u32(sV + r * VST + dseg * 4),
                     &Vb[(size_t)((c + 1) * 32 + r) * DIM + dseg * 4]);
            }
            CP_COMMIT();
        } else {
            CP_COMMIT();
        }
        CP_WAIT1();
        __syncthreads();
        const uint32_t* sV = (const uint32_t*)(dsm + ((c & 1) ? OFF_V1 : OFF_V0));
        #pragma unroll
        for (int kk = 0; kk < 32; kk += 8) {
            uint32_t af[2][4];
            #pragma unroll
            for (int mt = 0; mt < 2; mt++)
                ldsm_x4(af[mt][0], af[mt][1], af[mt][2], af[mt][3],
                        pBase + offP[mt] + (c * 32 + kk) * 4);
            uint32_t bf[8][2];
            #pragma unroll
            for (int nt = 0; nt < 8; nt++) {
                int d = nbase2 + nt * 8 + g;
                bf[nt][0] = sV[(kk + t) * VST + d];
                bf[nt][1] = sV[(kk + t + 4) * VST + d];
            }
            #pragma unroll
            for (int mt = 0; mt < 2; mt++)
                #pragma unroll
                for (int nt = 0; nt < 8; nt++)
                    mma_tf32(acc2[mt][nt], af[mt], bf[nt]);
        }
        __syncthreads();
    }

    #pragma unroll
    for (int mt = 0; mt < 2; mt++) {
        #pragma unroll
        for (int nt = 0; nt < 8; nt++) {
            int col = nbase2 + nt * 8 + 2 * t;
            int rr0 = l0 + mbase + mt * 16 + g;
            int rr1 = rr0 + 8;
            float* dst0 = &CTX[(size_t)(b * SEQ + rr0) * DIM + h * DHD + col];
            float* dst1 = &CTX[(size_t)(b * SEQ + rr1) * DIM + h * DHD + col];
            *reinterpret_cast<float2*>(dst0) = make_float2(acc2[mt][nt][0], acc2[mt][nt][1]);
            *reinterpret_cast<float2*>(dst1) = make_float2(acc2[mt][nt][2], acc2[mt][nt][3]);
        }
    }
}

// ---------------- fused weight prep: all transposes + dist pad --------------
__global__ void wprep(const float* __restrict__ Wq, const float* __restrict__ Wk,
                      const float* __restrict__ Wv, const float* __restrict__ Wo,
                      const float* __restrict__ Wi, const float* __restrict__ Wo2,
                      const float* __restrict__ dist,
                      float* __restrict__ WqT, float* __restrict__ WkT,
                      float* __restrict__ WvT, float* __restrict__ WoT,
                      float* __restrict__ WiT, float* __restrict__ Wo2T,
                      float* __restrict__ dPp) {
    int z = blockIdx.z;
    int i = blockIdx.x * 256 + threadIdx.x;
    if (z < 4) {
        const float* S = (z == 0) ? Wq : (z == 1) ? Wk : (z == 2) ? Wv : Wo;
        float* D       = (z == 0) ? WqT : (z == 1) ? WkT : (z == 2) ? WvT : WoT;
        int l = i >> 18;
        int w = i & 262143;
        int k = w >> 9, n = w & 511;
        D[(size_t)l * 262144 + n * 512 + k] = tf32_rna(S[i]);
    } else if (z == 4) {
        if (i < LNUM * DIM * FFI) {
            int l = i >> 16, w = i & 65535;
            int k = w >> 7, n = w & 127;
            WiT[(size_t)l * 65536 + n * 512 + k] = tf32_rna(Wi[i]);
        }
    } else if (z == 5) {
        if (i < LNUM * FFI * DIM) {
            int l = i >> 16, w = i & 65535;
            int k = w >> 9, n = w & 511;
            Wo2T[(size_t)l * 65536 + n * 128 + k] = tf32_rna(Wo2[i]);
        }
    } else {
        if (i < DPAD * DHD) {
            int pp = i >> 7;
            dPp[i] = (pp < 511) ? tf32_rna(dist[i]) : 0.0f;
        }
    }
}

// --------------------------- embedding + LN ---------------------------------
__device__ __forceinline__ void block_reduce2(float& a, float& b) {
    __shared__ float sa[8], sb[8];
    int lane = threadIdx.x & 31, w = threadIdx.x >> 5;
    #pragma unroll
    for (int o = 16; o; o >>= 1) {
        a += __shfl_xor_sync(0xffffffffu, a, o);
        b += __shfl_xor_sync(0xffffffffu, b, o);
    }
    if (lane == 0) { sa[w] = a; sb[w] = b; }
    __syncthreads();
    if (w == 0) {
        a = (lane < 8) ? sa[lane] : 0.0f;
        b = (lane < 8) ? sb[lane] : 0.0f;
        #pragma unroll
        for (int o = 4; o; o >>= 1) {
            a += __shfl_xor_sync(0xffffffffu, a, o);
            b += __shfl_xor_sync(0xffffffffu, b, o);
        }
        if (lane == 0) { sa[0] = a; sb[0] = b; }
    }
    __syncthreads();
    a = sa[0]; b = sb[0];
}

__global__ void embed_ln(const int* __restrict__ ids, const float* __restrict__ inW,
                         const float* __restrict__ inb, const float* __restrict__ tok,
                         const float* __restrict__ g,  const float* __restrict__ bb,
                         float* __restrict__ X) {
    int tt = blockIdx.x, tid = threadIdx.x;
    float f[NFEAT];
    #pragma unroll
    for (int i = 0; i < NFEAT; i++) f[i] = (float)ids[tt * NFEAT + i];
    int d0 = tid, d1 = tid + 256;
    float v0 = inb[d0] + tok[d0];
    float v1 = inb[d1] + tok[d1];
    #pragma unroll
    for (int i = 0; i < NFEAT; i++) {
        v0 += f[i] * inW[i * DIM + d0];
        v1 += f[i] * inW[i * DIM + d1];
    }
    float s = v0 + v1, q = v0 * v0 + v1 * v1;
    block_reduce2(s, q);
    float mu  = s * (1.0f / DIM);
    float var = q * (1.0f / DIM) - mu * mu;
    float r   = rsqrtf(var + 1e-12f);
    size_t base = (size_t)tt * DIM;
    X[base + d0] = (v0 - mu) * r * g[d0] + bb[d0];
    X[base + d1] = (v1 - mu) * r * g[d1] + bb[d1];
}

// warp-per-token pure LayerNorm
__global__ __launch_bounds__(256) void ln_w(
    const float* __restrict__ in,
    const float* __restrict__ g, const float* __restrict__ bb,
    float* __restrict__ out) {
    int wid = threadIdx.x >> 5, lane = threadIdx.x & 31;
    int tt = blockIdx.x * 8 + wid;
    size_t base = (size_t)tt * DIM;
    float4 v[4];
    float s = 0.0f, q = 0.0f;
    #pragma unroll
    for (int i = 0; i < 4; i++) {
        int col = i * 128 + lane * 4;
        v[i] = *reinterpret_cast<const float4*>(&in[base + col]);
        s += v[i].x + v[i].y + v[i].z + v[i].w;
        q += v[i].x * v[i].x + v[i].y * v[i].y + v[i].z * v[i].z + v[i].w * v[i].w;
    }
    #pragma unroll
    for (int o = 16; o; o >>= 1) {
        s += __shfl_xor_sync(0xffffffffu, s, o);
        q += __shfl_xor_sync(0xffffffffu, q, o);
    }
    float mu  = s * (1.0f / DIM);
    float var = q * (1.0f / DIM) - mu * mu;
    float r   = rsqrtf(var + 1e-12f);
    #pragma unroll
    for (int i = 0; i < 4; i++) {
        int col = i * 128 + lane * 4;
        float4 g4 = *reinterpret_cast<const float4*>(&g[col]);
        float4 b4 = *reinterpret_cast<const float4*>(&bb[col]);
        float4 o4;
        o4.x = (v[i].x - mu) * r * g4.x + b4.x;
        o4.y = (v[i].y - mu) * r * g4.y + b4.y;
        o4.z = (v[i].z - mu) * r * g4.z + b4.z;
        o4.w = (v[i].w - mu) * r * g4.w + b4.w;
        *reinterpret_cast<float4*>(&out[base + col]) = o4;
    }
}

// ------------------------------ host driver ----------------------------------
extern "C" void kernel_launch(void* const* d_in, const int* in_sizes, int n_in,
                              void* d_out, int out_size) {
    (void)in_sizes; (void)n_in; (void)out_size;
    const int*   ids  = (const int*)  d_in[0];
    const float* mask = (const float*)d_in[1];
    const float* inW  = (const float*)d_in[2];
    const float* inb  = (const float*)d_in[3];
    const float* tok  = (const float*)d_in[4];
    const float* elg  = (const float*)d_in[5];
    const float* elb  = (const float*)d_in[6];
    const float* dist = (const float*)d_in[7];
    const float* Wq   = (const float*)d_in[8];
    const float* bq   = (const float*)d_in[9];
    const float* Wk   = (const float*)d_in[10];
    const float* bk   = (const float*)d_in[11];
    const float* Wv   = (const float*)d_in[12];
    const float* bv   = (const float*)d_in[13];
    const float* Wo   = (const float*)d_in[14];
    const float* bo   = (const float*)d_in[15];
    const float* ln1g = (const float*)d_in[16];
    const float* ln1b = (const float*)d_in[17];
    const float* Wi   = (const float*)d_in[18];
    const float* bi   = (const float*)d_in[19];
    const float* Wo2  = (const float*)d_in[20];
    const float* bo2  = (const float*)d_in[21];
    const float* ln2g = (const float*)d_in[22];
    const float* ln2b = (const float*)d_in[23];
    float* out = (float*)d_out;

    float *X, *Q, *Kb, *V, *CTX, *TMP, *Hb, *QD, *KD, *dP;
    float *WqT, *WkT, *WvT, *WoT, *WiT, *Wo2T;
    cudaGetSymbolAddress((void**)&X,    g_X);
    cudaGetSymbolAddress((void**)&Q,    g_Q);
    cudaGetSymbolAddress((void**)&Kb,   g_K);
    cudaGetSymbolAddress((void**)&V,    g_V);
    cudaGetSymbolAddress((void**)&CTX,  g_CTX);
    cudaGetSymbolAddress((void**)&TMP,  g_TMP);
    cudaGetSymbolAddress((void**)&Hb,   g_Hb);
    cudaGetSymbolAddress((void**)&QD,   g_QD);
    cudaGetSymbolAddress((void**)&KD,   g_KD);
    cudaGetSymbolAddress((void**)&dP,   g_dP);
    cudaGetSymbolAddress((void**)&WqT,  g_WqT);
    cudaGetSymbolAddress((void**)&WkT,  g_WkT);
    cudaGetSymbolAddress((void**)&WvT,  g_WvT);
    cudaGetSymbolAddress((void**)&WoT,  g_WoT);
    cudaGetSymbolAddress((void**)&WiT,  g_WiT);
    cudaGetSymbolAddress((void**)&Wo2T, g_Wo2T);

    const int GEMM_SMEM  = NSTAGE * STAGEF * 4;
    const int FUSED_SMEM = FUSED_SMEMF * 4;
    cudaFuncSetAttribute(gemm_pipe<0,0,0>, cudaFuncAttributeMaxDynamicSharedMemorySize, GEMM_SMEM);
    cudaFuncSetAttribute(gemm_pipe<0,1,0>, cudaFuncAttributeMaxDynamicSharedMemorySize, GEMM_SMEM);
    cudaFuncSetAttribute(gemm_pipe<0,2,0>, cudaFuncAttributeMaxDynamicSharedMemorySize, GEMM_SMEM);
    cudaFuncSetAttribute(gemm_pipe<0,0,1>, cudaFuncAttributeMaxDynamicSharedMemorySize, GEMM_SMEM);
    cudaFuncSetAttribute(gemm_pipe<1,0,0>, cudaFuncAttributeMaxDynamicSharedMemorySize, GEMM_SMEM);
    cudaFuncSetAttribute(fused_attn,       cudaFuncAttributeMaxDynamicSharedMemorySize, FUSED_SMEM);

    wprep<<<dim3(4096, 1, 7), 256>>>(Wq, Wk, Wv, Wo, Wi, Wo2, dist,
                                     WqT, WkT, WvT, WoT, WiT, Wo2T, dP);
    embed_ln<<<TOK, 256>>>(ids, inW, inb, tok, elg, elb, X);

    dim3 gG(DIM / 128, TOK / 128);
    dim3 gGi(FFI / 128, TOK / 128);
    dim3 gQD(QCOLS / 128, ROWSBH / 128);
    dim3 gA(SEQ / 128, BATCH * NHEAD);

    for (int l = 0; l < LNUM; l++) {
        const float* wqt  = WqT  + (size_t)l * DIM * DIM;
        const float* wkt  = WkT  + (size_t)l * DIM * DIM;
        const float* wvt  = WvT  + (size_t)l * DIM * DIM;
        const float* wot  = WoT  + (size_t)l * DIM * DIM;
        const float* wit  = WiT  + (size_t)l * FFI * DIM;
        const float* wo2t = Wo2T + (size_t)l * DIM * FFI;

        gemm_pipe<0,0,0><<<gG, 256, GEMM_SMEM>>>(X, wqt, bq + l * DIM, nullptr, Q,  DIM, DIM);
        gemm_pipe<0,0,0><<<gG, 256, GEMM_SMEM>>>(X, wkt, bk + l * DIM, nullptr, Kb, DIM, DIM);
        gemm_pipe<0,0,0><<<gG, 256, GEMM_SMEM>>>(X, wvt, bv + l * DIM, nullptr, V,  DIM, DIM);

        gemm_pipe<0,1,0><<<gQD, 256, GEMM_SMEM>>>(Q,  dP, nullptr, nullptr, QD, DHD, QCOLS);
        gemm_pipe<0,2,0><<<gQD, 256, GEMM_SMEM>>>(Kb, dP, nullptr, nullptr, KD, DHD, QCOLS);

        fused_attn<<<gA, 256, FUSED_SMEM>>>(Q, Kb, V, QD, KD, mask, CTX);

        gemm_pipe<0,0,1><<<gG, 256, GEMM_SMEM>>>(CTX, wot, bo + l * DIM, X, TMP, DIM, DIM);
        ln_w<<<TOK / 8, 256>>>(TMP, ln1g + l * DIM, ln1b + l * DIM, X);

        gemm_pipe<1,0,0><<<gGi, 256, GEMM_SMEM>>>(X, wit, bi + l * FFI, nullptr, Hb, DIM, FFI);
        gemm_pipe<0,0,1><<<gG, 256, GEMM_SMEM>>>(Hb, wo2t, bo2 + l * DIM, X, TMP, FFI, DIM);
        ln_w<<<TOK / 8, 256>>>(TMP, ln2g + l * DIM, ln2b + l * DIM,
                               (l == LNUM - 1) ? out : X);
    }
}